// round 16
// baseline (speedup 1.0000x reference)
#include <cuda_runtime.h>
#include <cuda_fp16.h>
#include <math.h>
#include <stdint.h>

// Problem constants
#define S_DIM 512
#define N_DIM 384
#define CM 64
#define CZ 128
#define H_DIM 8
#define C_DIM 32
#define HC 256                  // H*C
#define SN (S_DIM * N_DIM)      // 196608 rows of m
#define M_DIM (S_DIM * C_DIM)   // 16384 = columns of the einsum GEMM
#define VROWS (N_DIM / 2)       // 192 j-pairs

// ---------------- scratch (device globals; no allocation allowed) ----------------
__device__ __half   g_mn16[SN * CM];                     // normalized m (fp16)      24 MB
__device__ uint32_t g_v32[H_DIM * VROWS * M_DIM];        // v pairs [h][j/2][m]     100 MB
__device__ __half   g_gate16[SN * HC];                   // gate fp16 [row][k]      100 MB
__device__ float    g_b[H_DIM * N_DIM * N_DIM];          // bias [h][j][i]          4.5 MB
__device__ __half   g_w16[H_DIM * N_DIM * N_DIM];        // softmax w [h][i][j]     2.4 MB
__device__ __half   g_wv16[H_DIM * N_DIM * M_DIM];       // wv fp16 [h][i][m]       100 MB
__device__ uint32_t g_w1h[(CM / 2) * HC];                // W1 pairs [k/2][256]
__device__ uint32_t g_w3h[(CM / 2) * HC];                // W3 pairs
__device__ uint32_t g_w4h[(HC / 2) * CM];                // W4 pairs [k/2][64]
__device__ float    g_w2t[H_DIM * CZ];                   // W2 transposed [h][k]

// ---------------- helpers ----------------
__device__ __forceinline__ uint32_t packh(float lo, float hi) {
    __half2 h = __floats2half2_rn(lo, hi);
    return *reinterpret_cast<uint32_t*>(&h);
}

__device__ __forceinline__ void mma16(float c[4], const uint32_t a[4], const uint32_t b[2]) {
    asm volatile(
        "mma.sync.aligned.m16n8k16.row.col.f32.f16.f16.f32 "
        "{%0,%1,%2,%3}, {%4,%5,%6,%7}, {%8,%9}, {%0,%1,%2,%3};\n"
        : "+f"(c[0]), "+f"(c[1]), "+f"(c[2]), "+f"(c[3])
        : "r"(a[0]), "r"(a[1]), "r"(a[2]), "r"(a[3]), "r"(b[0]), "r"(b[1]));
}

__device__ __forceinline__ uint32_t smem_u32(const void* p) {
    uint32_t a;
    asm("{ .reg .u64 t; cvta.to.shared.u64 t, %1; cvt.u32.u64 %0, t; }" : "=r"(a) : "l"(p));
    return a;
}
#define CP16(dst_u32, src_ptr) \
    asm volatile("cp.async.ca.shared.global [%0], [%1], 16;" \
                 :: "r"(dst_u32), "l"(src_ptr) : "memory")
#define CP_COMMIT() asm volatile("cp.async.commit_group;" ::: "memory")
#define CP_WAIT1()  asm volatile("cp.async.wait_group 1;" ::: "memory")
#define CP_WAIT0()  asm volatile("cp.async.wait_group 0;" ::: "memory")

// ---------------- K0: pack weights to fp16 pairs + transpose W2 ----------------
__global__ void round_weights(const float* __restrict__ W1,
                              const float* __restrict__ W3,
                              const float* __restrict__ W4,
                              const float* __restrict__ W2) {
    int i = blockIdx.x * blockDim.x + threadIdx.x;
    if (i < (CM / 2) * HC) {           // 8192
        int k2 = i >> 8, col = i & 255;
        g_w1h[i] = packh(W1[(2 * k2) * HC + col], W1[(2 * k2 + 1) * HC + col]);
        g_w3h[i] = packh(W3[(2 * k2) * HC + col], W3[(2 * k2 + 1) * HC + col]);
    }
    if (i < (HC / 2) * CM) {           // 8192
        int k2 = i >> 6, col = i & 63;
        g_w4h[i] = packh(W4[(2 * k2) * CM + col], W4[(2 * k2 + 1) * CM + col]);
    }
    if (i < H_DIM * CZ) {
        int h = i / CZ, k = i % CZ;
        g_w2t[i] = W2[k * H_DIM + h];
    }
}

// ---------------- K1a: LayerNorm over c_m=64, one warp per row -> fp16 ------------
__global__ void ln_m_kernel(const float* __restrict__ x,
                            const float* __restrict__ gamma,
                            const float* __restrict__ beta) {
    int warp = (blockIdx.x * blockDim.x + threadIdx.x) >> 5;
    int lane = threadIdx.x & 31;
    if (warp >= SN) return;
    float2 v  = *(const float2*)(x + (size_t)warp * CM + lane * 2);
    float2 gm = __ldg((const float2*)(gamma + lane * 2));
    float2 bt = __ldg((const float2*)(beta + lane * 2));
    float s  = v.x + v.y;
    float ss = v.x * v.x + v.y * v.y;
    #pragma unroll
    for (int o = 16; o > 0; o >>= 1) {
        s  += __shfl_xor_sync(0xffffffffu, s,  o);
        ss += __shfl_xor_sync(0xffffffffu, ss, o);
    }
    float mu  = s * (1.0f / 64.0f);
    float var = ss * (1.0f / 64.0f) - mu * mu;
    float inv = rsqrtf(var + 1e-5f);
    __half2 st = __floats2half2_rn((v.x - mu) * inv * gm.x + bt.x,
                                   (v.y - mu) * inv * gm.y + bt.y);
    *(__half2*)(g_mn16 + (size_t)warp * CM + lane * 2) = st;
}

// ============ fp16 GEMM machinery: 256 threads, 8 warps (2x4), warp tile 64x32 =======
// K-chunk 32: As fp16 rows, 32 halves = 16 words, pitch 20.
// Bs: k-pair words [j2=16][col=128], pitch 136.
struct TS {
    uint32_t As[128][20];
    uint32_t Bs[16][136];
};

__device__ __forceinline__ void mma_tile32h(float acc[4][4][4], const TS* sm,
                                            int wm, int wn, int g, int tig) {
    #pragma unroll
    for (int sub = 0; sub < 2; sub++) {
        uint32_t af[4][4], bf[4][2];
        #pragma unroll
        for (int mt = 0; mt < 4; mt++) {
            int r = wm * 64 + mt * 16;
            af[mt][0] = sm->As[r + g][sub * 8 + tig];
            af[mt][1] = sm->As[r + g + 8][sub * 8 + tig];
            af[mt][2] = sm->As[r + g][sub * 8 + tig + 4];
            af[mt][3] = sm->As[r + g + 8][sub * 8 + tig + 4];
        }
        #pragma unroll
        for (int nt = 0; nt < 4; nt++) {
            int cc = wn * 32 + nt * 8 + g;
            bf[nt][0] = sm->Bs[sub * 8 + tig][cc];
            bf[nt][1] = sm->Bs[sub * 8 + tig + 4][cc];
        }
        #pragma unroll
        for (int mt = 0; mt < 4; mt++)
            #pragma unroll
            for (int nt = 0; nt < 4; nt++)
                mma16(acc[mt][nt], af[mt], bf[nt]);
    }
}

// cp.async staging (chunk of 32 k): A 128 rows x 32 halves, B 16 j2-rows x 128 words.
__device__ __forceinline__ void stage_f16(uint32_t sA, uint32_t sB, int t,
                                          const __half* aptr, size_t lda_h,
                                          const uint32_t* bptr, size_t ldb_w) {
    #pragma unroll
    for (int u = 0; u < 2; u++) {
        int idx = t + u * 256;
        int row = idx >> 2, kc = idx & 3;
        CP16(sA + (uint32_t)(row * 20 + kc * 4) * 4, aptr + (size_t)row * lda_h + kc * 8);
    }
    #pragma unroll
    for (int u = 0; u < 2; u++) {
        int idx = t + u * 256;
        int j2 = idx >> 5, mc = (idx & 31) * 4;
        CP16(sB + (uint32_t)(j2 * 136 + mc) * 4, bptr + (size_t)j2 * ldb_w + mc);
    }
}

// ---------------- K1b: fp16-MMA GEMM [SN x 64] @ [64 x 512] -> v pairs + gate -------
__global__ __launch_bounds__(256, 2) void gemm_mw_mma() {
    __shared__ TS sm[2];
    int t = threadIdx.x;
    int lane = t & 31, w = t >> 5;
    int wm = w & 1, wn = w >> 1;
    int g = lane >> 2, tig = lane & 3;
    int i0 = blockIdx.x * 128;
    int cy = blockIdx.y;                          // 0,1 -> W1 halves ; 2,3 -> W3 halves
    const uint32_t* B = (cy < 2) ? g_w1h : g_w3h;
    int col0 = (cy & 1) * 128;

    uint32_t sA[2] = {smem_u32(sm[0].As), smem_u32(sm[1].As)};
    uint32_t sB[2] = {smem_u32(sm[0].Bs), smem_u32(sm[1].Bs)};

    float acc[4][4][4];
    #pragma unroll
    for (int a = 0; a < 4; a++)
        #pragma unroll
        for (int b = 0; b < 4; b++)
            #pragma unroll
            for (int q = 0; q < 4; q++) acc[a][b][q] = 0.0f;

    const __half* Abase = g_mn16 + (size_t)i0 * CM;
    const uint32_t* Bbase = B + col0;

    stage_f16(sA[0], sB[0], t, Abase, CM, Bbase, HC);
    CP_COMMIT();

    #pragma unroll 1
    for (int c = 0; c < 2; c++) {
        int b = c & 1;
        if (c + 1 < 2)
            stage_f16(sA[1 - b], sB[1 - b], t,
                      Abase + (c + 1) * 32, CM,
                      Bbase + (size_t)(c + 1) * 16 * HC, HC);
        CP_COMMIT();
        if (c + 1 < 2) { CP_WAIT1(); } else { CP_WAIT0(); }
        __syncthreads();
        mma_tile32h(acc, &sm[b], wm, wn, g, tig);
        __syncthreads();
    }

    // epilogue: v (j-pair packed via shfl) or sigmoid gate (fp16)
    #pragma unroll
    for (int mt = 0; mt < 4; mt++) {
        #pragma unroll
        for (int half = 0; half < 2; half++) {
            int i = i0 + wm * 64 + mt * 16 + g + half * 8;
            int s = i / N_DIM, n = i % N_DIM;
            #pragma unroll
            for (int nt = 0; nt < 4; nt++) {
                int colp = wn * 32 + nt * 8 + 2 * tig;
                float v0 = acc[mt][nt][half * 2];
                float v1 = acc[mt][nt][half * 2 + 1];
                if (cy < 2) {
                    float p0 = __shfl_down_sync(0xffffffffu, v0, 4);
                    float p1 = __shfl_down_sync(0xffffffffu, v1, 4);
                    if (!(g & 1)) {
                        int colg = cy * 128 + colp;
                        int hh = colg >> 5, cc = colg & 31;
                        uint2 st = {packh(v0, p0), packh(v1, p1)};
                        *(uint2*)&g_v32[(size_t)hh * (VROWS * M_DIM) +
                                        (size_t)(n >> 1) * M_DIM + s * C_DIM + cc] = st;
                    }
                } else {
                    float s0 = 1.0f / (1.0f + __expf(-v0));
                    float s1 = 1.0f / (1.0f + __expf(-v1));
                    ((uint32_t*)g_gate16)[(size_t)i * 128 + (cy - 2) * 64 +
                                          wn * 16 + nt * 4 + tig] = packh(s0, s1);
                }
            }
        }
    }
}

// ---------------- K2: warp-per-8-rows LN(z) + @W2t -> b[h][j][i] ----------------
#define LNZ_ROWS 8
__global__ __launch_bounds__(256) void ln_z_warp(const float* __restrict__ z,
                                                 const float* __restrict__ gz,
                                                 const float* __restrict__ bz) {
    int wg = (blockIdx.x * blockDim.x + threadIdx.x) >> 5;
    int lane = threadIdx.x & 31;
    int row0 = wg * LNZ_ROWS;
    if (row0 >= N_DIM * N_DIM) return;

    float4 gm = __ldg((const float4*)(gz + lane * 4));
    float4 bt = __ldg((const float4*)(bz + lane * 4));
    float4 w2[H_DIM];
    #pragma unroll
    for (int h = 0; h < H_DIM; h++)
        w2[h] = __ldg((const float4*)(g_w2t + h * CZ + lane * 4));

    #pragma unroll 1
    for (int r = 0; r < LNZ_ROWS; r++) {
        int row = row0 + r;
        int i = row / N_DIM, j = row % N_DIM;

        float4 x = *(const float4*)(z + (size_t)row * CZ + lane * 4);
        float s  = x.x + x.y + x.z + x.w;
        float ss = x.x * x.x + x.y * x.y + x.z * x.z + x.w * x.w;
        #pragma unroll
        for (int o = 16; o > 0; o >>= 1) {
            s  += __shfl_xor_sync(0xffffffffu, s,  o);
            ss += __shfl_xor_sync(0xffffffffu, ss, o);
        }
        float mu  = s * (1.0f / 128.0f);
        float var = ss * (1.0f / 128.0f) - mu * mu;
        float inv = rsqrtf(var + 1e-5f);

        float zn0 = (x.x - mu) * inv * gm.x + bt.x;
        float zn1 = (x.y - mu) * inv * gm.y + bt.y;
        float zn2 = (x.z - mu) * inv * gm.z + bt.z;
        float zn3 = (x.w - mu) * inv * gm.w + bt.w;

        float acc[H_DIM];
        #pragma unroll
        for (int h = 0; h < H_DIM; h++)
            acc[h] = zn0 * w2[h].x + zn1 * w2[h].y + zn2 * w2[h].z + zn3 * w2[h].w;

        // fold head index into lane index: xor16 (head bit2), xor8 (bit1), xor4 (bit0)
        #pragma unroll
        for (int h = 0; h < 4; h++) {
            float v = (lane & 16) ? acc[h] : acc[h + 4];
            float o = __shfl_xor_sync(0xffffffffu, v, 16);
            acc[h] = ((lane & 16) ? acc[h + 4] : acc[h]) + o;
        }
        #pragma unroll
        for (int h = 0; h < 2; h++) {
            float v = (lane & 8) ? acc[h] : acc[h + 2];
            float o = __shfl_xor_sync(0xffffffffu, v, 8);
            acc[h] = ((lane & 8) ? acc[h + 2] : acc[h]) + o;
        }
        {
            float v = (lane & 4) ? acc[0] : acc[1];
            float o = __shfl_xor_sync(0xffffffffu, v, 4);
            acc[0] = ((lane & 4) ? acc[1] : acc[0]) + o;
        }
        acc[0] += __shfl_xor_sync(0xffffffffu, acc[0], 2);
        acc[0] += __shfl_xor_sync(0xffffffffu, acc[0], 1);

        if ((lane & 3) == 0) {
            int h = lane >> 2;
            g_b[((size_t)h * N_DIM + j) * N_DIM + i] = acc[0];
        }
    }
}

// ---------------- K3: softmax over i, write w[h][i][j] fp16 -----------------------
__global__ void softmax_kernel() {
    __shared__ float redm[4];
    __shared__ float reds[4];
    int j = blockIdx.x;
    int h = blockIdx.y;
    int t = threadIdx.x;
    const float* col = g_b + ((size_t)h * N_DIM + j) * N_DIM;
    float v0 = col[t], v1 = col[t + 128], v2 = col[t + 256];
    float mx = fmaxf(v0, fmaxf(v1, v2));
    #pragma unroll
    for (int o = 16; o > 0; o >>= 1) mx = fmaxf(mx, __shfl_xor_sync(0xffffffffu, mx, o));
    int warp = t >> 5, lane = t & 31;
    if (lane == 0) redm[warp] = mx;
    __syncthreads();
    mx = fmaxf(fmaxf(redm[0], redm[1]), fmaxf(redm[2], redm[3]));
    float e0 = __expf(v0 - mx), e1 = __expf(v1 - mx), e2 = __expf(v2 - mx);
    float sm = e0 + e1 + e2;
    #pragma unroll
    for (int o = 16; o > 0; o >>= 1) sm += __shfl_xor_sync(0xffffffffu, sm, o);
    if (lane == 0) reds[warp] = sm;
    __syncthreads();
    float inv = 1.0f / (reds[0] + reds[1] + reds[2] + reds[3]);
    __half* wbase = g_w16 + (size_t)h * N_DIM * N_DIM + j;
    wbase[(size_t)(t)       * N_DIM] = __float2half(e0 * inv);
    wbase[(size_t)(t + 128) * N_DIM] = __float2half(e1 * inv);
    wbase[(size_t)(t + 256) * N_DIM] = __float2half(e2 * inv);
}

// ---------------- K4: fp16-MMA per-head GEMM  wv_h[i,m] = w_h[i,j] @ v_h[j,m] ------
__global__ __launch_bounds__(256, 2) void gemm_wv_mma() {
    __shared__ TS sm[2];
    int t = threadIdx.x;
    int lane = t & 31, w = t >> 5;
    int wm = w & 1, wn = w >> 1;
    int g = lane >> 2, tig = lane & 3;
    int i0 = blockIdx.x * 128;           // 3 i-tiles (fastest -> v-tile L2 reuse)
    int m0 = blockIdx.y * 128;           // 128 m-tiles
    int h  = blockIdx.z;
    const __half* A = g_w16 + (size_t)h * N_DIM * N_DIM;              // [i][j] fp16
    const uint32_t* Bv = g_v32 + (size_t)h * (VROWS * M_DIM);         // [j2][m] pairs

    uint32_t sA[2] = {smem_u32(sm[0].As), smem_u32(sm[1].As)};
    uint32_t sB[2] = {smem_u32(sm[0].Bs), smem_u32(sm[1].Bs)};

    float acc[4][4][4];
    #pragma unroll
    for (int a = 0; a < 4; a++)
        #pragma unroll
        for (int b = 0; b < 4; b++)
            #pragma unroll
            for (int q = 0; q < 4; q++) acc[a][b][q] = 0.0f;

    const __half* Abase = A + (size_t)i0 * N_DIM;
    const uint32_t* Bbase = Bv + m0;

    stage_f16(sA[0], sB[0], t, Abase, N_DIM, Bbase, M_DIM);
    CP_COMMIT();

    #pragma unroll 1
    for (int c = 0; c < 12; c++) {
        int b = c & 1;
        if (c + 1 < 12)
            stage_f16(sA[1 - b], sB[1 - b], t,
                      Abase + (c + 1) * 32, N_DIM,
                      Bbase + (size_t)(c + 1) * 16 * M_DIM, M_DIM);
        CP_COMMIT();
        if (c + 1 < 12) { CP_WAIT1(); } else { CP_WAIT0(); }
        __syncthreads();
        mma_tile32h(acc, &sm[b], wm, wn, g, tig);
        __syncthreads();
    }

    uint32_t* dsth = (uint32_t*)g_wv16 + (size_t)h * N_DIM * (M_DIM / 2);
    #pragma unroll
    for (int mt = 0; mt < 4; mt++) {
        int r = i0 + wm * 64 + mt * 16 + g;
        #pragma unroll
        for (int nt = 0; nt < 4; nt++) {
            int colw = (m0 + wn * 32 + nt * 8 + 2 * tig) >> 1;
            dsth[(size_t)r * (M_DIM / 2) + colw] =
                packh(acc[mt][nt][0], acc[mt][nt][1]);
            dsth[(size_t)(r + 8) * (M_DIM / 2) + colw] =
                packh(acc[mt][nt][2], acc[mt][nt][3]);
        }
    }
}

// ---------------- K5: fp16-MMA  out[r,64] = (gate*wv_gather) @ W4 ------------------
// Full W4 staged once (128 k2-rows x 64 words, pitch 68); Os double-buffered;
// ONE sync per chunk; next chunk's LDGs issued before the sync.
#define K5_OS_WORDS (2 * 128 * 20)
#define K5_SMEM ((K5_OS_WORDS + 128 * 68) * 4)
__global__ __launch_bounds__(256) void final_mma(float* __restrict__ out) {
    extern __shared__ uint32_t dyn5[];
    uint32_t (*Os)[20] = (uint32_t(*)[20])dyn5;                 // [2*128][20]
    uint32_t (*Ws)[68] = (uint32_t(*)[68])(dyn5 + K5_OS_WORDS); // [128][68]
    int t = threadIdx.x;
    int lane = t & 31, w = t >> 5;
    int wm = w >> 1, wn = w & 1;
    int g = lane >> 2, tig = lane & 3;
    int r0 = blockIdx.x * 128;

    // stage ALL of W4 once via cp.async
    {
        uint32_t wsb = smem_u32(Ws);
        #pragma unroll
        for (int u = 0; u < 8; u++) {
            int idx = t + u * 256;
            int kr = idx >> 4, cw = (idx & 15) * 4;
            CP16(wsb + (uint32_t)(kr * 68 + cw) * 4, g_w4h + (size_t)kr * CM + cw);
        }
        CP_COMMIT();
    }

    float acc[2][4][4];
    #pragma unroll
    for (int a = 0; a < 2; a++)
        #pragma unroll
        for (int b = 0; b < 4; b++)
            #pragma unroll
            for (int q = 0; q < 4; q++) acc[a][b][q] = 0.0f;

    int row = t >> 1, kh = (t & 1) * 16;
    int rr = r0 + row;
    int sI = rr / N_DIM, nI = rr % N_DIM;
    const uint32_t* gtbase = (const uint32_t*)g_gate16 + ((size_t)rr * HC + kh) / 2;

    // preload chunk 0
    uint4 wv0, wv1, gt0, gt1;
    {
        const uint32_t* wvp = (const uint32_t*)g_wv16 +
            ((size_t)(0 * N_DIM + nI) * M_DIM + sI * C_DIM + kh) / 2;
        wv0 = *(const uint4*)wvp;
        wv1 = *(const uint4*)(wvp + 4);
        gt0 = *(const uint4*)gtbase;
        gt1 = *(const uint4*)(gtbase + 4);
    }
    CP_WAIT0();

    #pragma unroll 1
    for (int c = 0; c < 8; c++) {
        // products -> Os buffer c&1
        {
            uint32_t* d = &Os[(c & 1) * 128 + row][(t & 1) * 8];
            const uint32_t* wvw = (const uint32_t*)&wv0;
            const uint32_t* gtw = (const uint32_t*)&gt0;
            #pragma unroll
            for (int u = 0; u < 4; u++) {
                __half2 p = __hmul2(*(const __half2*)&wvw[u], *(const __half2*)&gtw[u]);
                d[u] = *(uint32_t*)&p;
            }
            const uint32_t* wvw1 = (const uint32_t*)&wv1;
            const uint32_t* gtw1 = (const uint32_t*)&gt1;
            #pragma unroll
            for (int u = 0; u < 4; u++) {
                __half2 p = __hmul2(*(const __half2*)&wvw1[u], *(const __half2*)&gtw1[u]);
                d[4 + u] = *(uint32_t*)&p;
            }
        }
        // issue next chunk's loads before the barrier
        if (c + 1 < 8) {
            const uint32_t* wvp = (const uint32_t*)g_wv16 +
                ((size_t)((c + 1) * N_DIM + nI) * M_DIM + sI * C_DIM + kh) / 2;
            wv0 = *(const uint4*)wvp;
            wv1 = *(const uint4*)(wvp + 4);
            gt0 = *(const uint4*)(gtbase + (c + 1) * 16);
            gt1 = *(const uint4*)(gtbase + (c + 1) * 16 + 4);
        }
        __syncthreads();
        // mma on buffer c&1, W4 rows for head c
        const uint32_t (*Ob)[20] = (const uint32_t(*)[20])&Os[(c & 1) * 128];
        #pragma unroll
        for (int kc = 0; kc < 2; kc++) {
            uint32_t af[2][4], bf[4][2];
            #pragma unroll
            for (int mt = 0; mt < 2; mt++) {
                int r = wm * 32 + mt * 16;
                af[mt][0] = Ob[r + g][kc * 8 + tig];
                af[mt][1] = Ob[r + g + 8][kc * 8 + tig];
                af[mt][2] = Ob[r + g][kc * 8 + tig + 4];
                af[mt][3] = Ob[r + g + 8][kc * 8 + tig + 4];
            }
            #pragma unroll
            for (int nt = 0; nt < 4; nt++) {
                int cc = wn * 32 + nt * 8 + g;
                bf[nt][0] = Ws[c * 16 + kc * 8 + tig][cc];
                bf[nt][1] = Ws[c * 16 + kc * 8 + tig + 4][cc];
            }
            #pragma unroll
            for (int mt = 0; mt < 2; mt++)
                #pragma unroll
                for (int nt = 0; nt < 4; nt++)
                    mma16(acc[mt][nt], af[mt], bf[nt]);
        }
    }

    #pragma unroll
    for (int mt = 0; mt < 2; mt++) {
        int r = r0 + wm * 32 + mt * 16 + g;
        #pragma unroll
        for (int nt = 0; nt < 4; nt++) {
            int col = wn * 32 + nt * 8 + 2 * tig;
            float2 v0 = {acc[mt][nt][0], acc[mt][nt][1]};
            float2 v1 = {acc[mt][nt][2], acc[mt][nt][3]};
            *(float2*)(out + (size_t)r * CM + col) = v0;
            *(float2*)(out + (size_t)(r + 8) * CM + col) = v1;
        }
    }
}

// ---------------- launch ----------------
extern "C" void kernel_launch(void* const* d_in, const int* in_sizes, int n_in,
                              void* d_out, int out_size) {
    const float* m_si    = (const float*)d_in[0];
    const float* z_ij    = (const float*)d_in[1];
    const float* gamma_m = (const float*)d_in[2];
    const float* beta_m  = (const float*)d_in[3];
    const float* W1      = (const float*)d_in[4];
    const float* gamma_z = (const float*)d_in[5];
    const float* beta_z  = (const float*)d_in[6];
    const float* W2      = (const float*)d_in[7];
    const float* W3      = (const float*)d_in[8];
    const float* W4      = (const float*)d_in[9];
    float* out = (float*)d_out;

    cudaFuncSetAttribute(final_mma, cudaFuncAttributeMaxDynamicSharedMemorySize, K5_SMEM);

    // order: gemm_mw at launch #4 so the ncu capture (-s 5) profiles a GEMM
    round_weights<<<32, 256>>>(W1, W3, W4, W2);
    ln_m_kernel<<<SN / 8, 256>>>(m_si, gamma_m, beta_m);
    ln_z_warp<<<(N_DIM * N_DIM) / (8 * LNZ_ROWS), 256>>>(z_ij, gamma_z, beta_z);
    gemm_mw_mma<<<dim3(SN / 128, 4), 256>>>();
    softmax_kernel<<<dim3(N_DIM, H_DIM), 128>>>();
    gemm_wv_mma<<<dim3(N_DIM / 128, M_DIM / 128, H_DIM), 256>>>();
    final_mma<<<SN / 128, 256, K5_SMEM>>>(out);
}

// round 17
// speedup vs baseline: 1.0331x; 1.0331x over previous
#include <cuda_runtime.h>
#include <cuda_fp16.h>
#include <math.h>
#include <stdint.h>

// Problem constants
#define S_DIM 512
#define N_DIM 384
#define CM 64
#define CZ 128
#define H_DIM 8
#define C_DIM 32
#define HC 256                  // H*C
#define SN (S_DIM * N_DIM)      // 196608 rows of m
#define M_DIM (S_DIM * C_DIM)   // 16384 = columns of the einsum GEMM
#define VROWS (N_DIM / 2)       // 192 j-pairs

// ---------------- scratch (device globals; no allocation allowed) ----------------
__device__ __half   g_mn16[SN * CM];                     // normalized m (fp16)      24 MB
__device__ uint32_t g_v32[H_DIM * VROWS * M_DIM];        // v pairs [h][j/2][m]     100 MB
__device__ __half   g_gate16[SN * HC];                   // gate fp16 [row][k]      100 MB
__device__ float    g_b[H_DIM * N_DIM * N_DIM];          // bias [h][j][i]          4.5 MB
__device__ __half   g_w16[H_DIM * N_DIM * N_DIM];        // softmax w [h][i][j]     2.4 MB
__device__ __half   g_wv16[H_DIM * N_DIM * M_DIM];       // wv fp16 [h][i][m]       100 MB
__device__ uint32_t g_w1h[(CM / 2) * HC];                // W1 pairs [k/2][256]
__device__ uint32_t g_w3h[(CM / 2) * HC];                // W3 pairs
__device__ uint32_t g_w4h[(HC / 2) * CM];                // W4 pairs [k/2][64]
__device__ float    g_w2t[H_DIM * CZ];                   // W2 transposed [h][k]

// ---------------- helpers ----------------
__device__ __forceinline__ uint32_t packh(float lo, float hi) {
    __half2 h = __floats2half2_rn(lo, hi);
    return *reinterpret_cast<uint32_t*>(&h);
}

__device__ __forceinline__ void mma16(float c[4], const uint32_t a[4], const uint32_t b[2]) {
    asm volatile(
        "mma.sync.aligned.m16n8k16.row.col.f32.f16.f16.f32 "
        "{%0,%1,%2,%3}, {%4,%5,%6,%7}, {%8,%9}, {%0,%1,%2,%3};\n"
        : "+f"(c[0]), "+f"(c[1]), "+f"(c[2]), "+f"(c[3])
        : "r"(a[0]), "r"(a[1]), "r"(a[2]), "r"(a[3]), "r"(b[0]), "r"(b[1]));
}

__device__ __forceinline__ uint32_t smem_u32(const void* p) {
    uint32_t a;
    asm("{ .reg .u64 t; cvta.to.shared.u64 t, %1; cvt.u32.u64 %0, t; }" : "=r"(a) : "l"(p));
    return a;
}
#define CP16(dst_u32, src_ptr) \
    asm volatile("cp.async.ca.shared.global [%0], [%1], 16;" \
                 :: "r"(dst_u32), "l"(src_ptr) : "memory")
#define CP_COMMIT() asm volatile("cp.async.commit_group;" ::: "memory")
#define CP_WAIT1()  asm volatile("cp.async.wait_group 1;" ::: "memory")
#define CP_WAIT0()  asm volatile("cp.async.wait_group 0;" ::: "memory")

// ---------------- K0: pack weights to fp16 pairs + transpose W2 ----------------
__global__ void round_weights(const float* __restrict__ W1,
                              const float* __restrict__ W3,
                              const float* __restrict__ W4,
                              const float* __restrict__ W2) {
    int i = blockIdx.x * blockDim.x + threadIdx.x;
    if (i < (CM / 2) * HC) {           // 8192
        int k2 = i >> 8, col = i & 255;
        g_w1h[i] = packh(W1[(2 * k2) * HC + col], W1[(2 * k2 + 1) * HC + col]);
        g_w3h[i] = packh(W3[(2 * k2) * HC + col], W3[(2 * k2 + 1) * HC + col]);
    }
    if (i < (HC / 2) * CM) {           // 8192
        int k2 = i >> 6, col = i & 63;
        g_w4h[i] = packh(W4[(2 * k2) * CM + col], W4[(2 * k2 + 1) * CM + col]);
    }
    if (i < H_DIM * CZ) {
        int h = i / CZ, k = i % CZ;
        g_w2t[i] = W2[k * H_DIM + h];
    }
}

// ---------------- K1a: LayerNorm over c_m=64, one warp per row -> fp16 ------------
__global__ void ln_m_kernel(const float* __restrict__ x,
                            const float* __restrict__ gamma,
                            const float* __restrict__ beta) {
    int warp = (blockIdx.x * blockDim.x + threadIdx.x) >> 5;
    int lane = threadIdx.x & 31;
    if (warp >= SN) return;
    float2 v  = *(const float2*)(x + (size_t)warp * CM + lane * 2);
    float2 gm = __ldg((const float2*)(gamma + lane * 2));
    float2 bt = __ldg((const float2*)(beta + lane * 2));
    float s  = v.x + v.y;
    float ss = v.x * v.x + v.y * v.y;
    #pragma unroll
    for (int o = 16; o > 0; o >>= 1) {
        s  += __shfl_xor_sync(0xffffffffu, s,  o);
        ss += __shfl_xor_sync(0xffffffffu, ss, o);
    }
    float mu  = s * (1.0f / 64.0f);
    float var = ss * (1.0f / 64.0f) - mu * mu;
    float inv = rsqrtf(var + 1e-5f);
    __half2 st = __floats2half2_rn((v.x - mu) * inv * gm.x + bt.x,
                                   (v.y - mu) * inv * gm.y + bt.y);
    *(__half2*)(g_mn16 + (size_t)warp * CM + lane * 2) = st;
}

// ============ fp16 GEMM machinery: 256 threads, 8 warps (2x4), warp tile 64x32 =======
#define AF_PITCH 36
struct TS {
    uint32_t As[128][20];
    uint32_t Bs[16][136];
};

__device__ __forceinline__ void mma_tile32h(float acc[4][4][4], const TS* sm,
                                            int wm, int wn, int g, int tig) {
    #pragma unroll
    for (int sub = 0; sub < 2; sub++) {
        uint32_t af[4][4], bf[4][2];
        #pragma unroll
        for (int mt = 0; mt < 4; mt++) {
            int r = wm * 64 + mt * 16;
            af[mt][0] = sm->As[r + g][sub * 8 + tig];
            af[mt][1] = sm->As[r + g + 8][sub * 8 + tig];
            af[mt][2] = sm->As[r + g][sub * 8 + tig + 4];
            af[mt][3] = sm->As[r + g + 8][sub * 8 + tig + 4];
        }
        #pragma unroll
        for (int nt = 0; nt < 4; nt++) {
            int cc = wn * 32 + nt * 8 + g;
            bf[nt][0] = sm->Bs[sub * 8 + tig][cc];
            bf[nt][1] = sm->Bs[sub * 8 + tig + 4][cc];
        }
        #pragma unroll
        for (int mt = 0; mt < 4; mt++)
            #pragma unroll
            for (int nt = 0; nt < 4; nt++)
                mma16(acc[mt][nt], af[mt], bf[nt]);
    }
}

// mma one 32-K chunk against the resident full-A tile (chunk ck selects word range)
__device__ __forceinline__ void mma_af(float acc[4][4][4],
                                       const uint32_t (*Af)[AF_PITCH],
                                       const uint32_t (*Bs)[136],
                                       int ck, int wm, int wn, int g, int tig) {
    #pragma unroll
    for (int sub = 0; sub < 2; sub++) {
        int base = ck * 16 + sub * 8;
        uint32_t af[4][4], bf[4][2];
        #pragma unroll
        for (int mt = 0; mt < 4; mt++) {
            int r = wm * 64 + mt * 16;
            af[mt][0] = Af[r + g][base + tig];
            af[mt][1] = Af[r + g + 8][base + tig];
            af[mt][2] = Af[r + g][base + tig + 4];
            af[mt][3] = Af[r + g + 8][base + tig + 4];
        }
        #pragma unroll
        for (int nt = 0; nt < 4; nt++) {
            int cc = wn * 32 + nt * 8 + g;
            bf[nt][0] = Bs[sub * 8 + tig][cc];
            bf[nt][1] = Bs[sub * 8 + tig + 4][cc];
        }
        #pragma unroll
        for (int mt = 0; mt < 4; mt++)
            #pragma unroll
            for (int nt = 0; nt < 4; nt++)
                mma16(acc[mt][nt], af[mt], bf[nt]);
    }
}

// cp.async staging (chunk of 32 k): A 128 rows x 32 halves, B 16 j2-rows x 128 words.
__device__ __forceinline__ void stage_f16(uint32_t sA, uint32_t sB, int t,
                                          const __half* aptr, size_t lda_h,
                                          const uint32_t* bptr, size_t ldb_w) {
    #pragma unroll
    for (int u = 0; u < 2; u++) {
        int idx = t + u * 256;
        int row = idx >> 2, kc = idx & 3;
        CP16(sA + (uint32_t)(row * 20 + kc * 4) * 4, aptr + (size_t)row * lda_h + kc * 8);
    }
    #pragma unroll
    for (int u = 0; u < 2; u++) {
        int idx = t + u * 256;
        int j2 = idx >> 5, mc = (idx & 31) * 4;
        CP16(sB + (uint32_t)(j2 * 136 + mc) * 4, bptr + (size_t)j2 * ldb_w + mc);
    }
}

__device__ __forceinline__ void stage_b_only(uint32_t sB, int t, const uint32_t* bptr) {
    #pragma unroll
    for (int u = 0; u < 2; u++) {
        int idx = t + u * 256;
        int j2 = idx >> 5, mc = (idx & 31) * 4;
        CP16(sB + (uint32_t)(j2 * 136 + mc) * 4, bptr + (size_t)j2 * HC + mc);
    }
}

// ---------------- K1b: merged fp16-MMA GEMM [SN x 64] @ [64 x 512] ------------------
// One CTA per 128-row tile; A staged ONCE; loops 4 B-tiles (W1 lo/hi, W3 lo/hi).
__global__ __launch_bounds__(256, 2) void gemm_mw_mma() {
    __shared__ uint32_t Af[128][AF_PITCH];     // full A tile: 64 halves = 32 words
    __shared__ uint32_t Bsbuf[2][16][136];
    int t = threadIdx.x;
    int lane = t & 31, w = t >> 5;
    int wm = w & 1, wn = w >> 1;
    int g = lane >> 2, tig = lane & 3;
    int i0 = blockIdx.x * 128;

    uint32_t afb = smem_u32(Af);
    uint32_t bsb[2] = {smem_u32(Bsbuf[0]), smem_u32(Bsbuf[1])};

    // stage full A tile (128 x 64 halves = 1024 16B-chunks, 4/thread)
    const __half* Abase = g_mn16 + (size_t)i0 * CM;
    #pragma unroll
    for (int u = 0; u < 4; u++) {
        int idx = t + u * 256;
        int row = idx >> 3, kc = idx & 7;
        CP16(afb + (uint32_t)(row * AF_PITCH + kc * 4) * 4,
             Abase + (size_t)row * CM + kc * 8);
    }
    // stage B for q=0 (cy=0, chunk 0)
    stage_b_only(bsb[0], t, g_w1h);
    CP_COMMIT();

    float acc[4][4][4];
    #pragma unroll
    for (int a = 0; a < 4; a++)
        #pragma unroll
        for (int b = 0; b < 4; b++)
            #pragma unroll
            for (int q = 0; q < 4; q++) acc[a][b][q] = 0.0f;

    #pragma unroll 1
    for (int q = 0; q < 8; q++) {
        int b = q & 1;
        if (q + 1 < 8) {
            int cy1 = (q + 1) >> 1, c1 = (q + 1) & 1;
            const uint32_t* Bsrc = ((cy1 < 2) ? g_w1h : g_w3h) +
                                   (cy1 & 1) * 128 + (size_t)(c1 * 16) * HC;
            stage_b_only(bsb[1 - b], t, Bsrc);
        }
        CP_COMMIT();
        if (q + 1 < 8) { CP_WAIT1(); } else { CP_WAIT0(); }
        __syncthreads();
        mma_af(acc, Af, Bsbuf[b], q & 1, wm, wn, g, tig);
        __syncthreads();

        if (q & 1) {
            int cy = q >> 1;
            // epilogue for this cy: v (j-pair packed) or sigmoid gate
            #pragma unroll
            for (int mt = 0; mt < 4; mt++) {
                #pragma unroll
                for (int half = 0; half < 2; half++) {
                    int i = i0 + wm * 64 + mt * 16 + g + half * 8;
                    int s = i / N_DIM, n = i % N_DIM;
                    #pragma unroll
                    for (int nt = 0; nt < 4; nt++) {
                        int colp = wn * 32 + nt * 8 + 2 * tig;
                        float v0 = acc[mt][nt][half * 2];
                        float v1 = acc[mt][nt][half * 2 + 1];
                        if (cy < 2) {
                            float p0 = __shfl_down_sync(0xffffffffu, v0, 4);
                            float p1 = __shfl_down_sync(0xffffffffu, v1, 4);
                            if (!(g & 1)) {
                                int colg = cy * 128 + colp;
                                int hh = colg >> 5, cc = colg & 31;
                                uint2 st = {packh(v0, p0), packh(v1, p1)};
                                *(uint2*)&g_v32[(size_t)hh * (VROWS * M_DIM) +
                                                (size_t)(n >> 1) * M_DIM + s * C_DIM + cc] = st;
                            }
                        } else {
                            float s0 = 1.0f / (1.0f + __expf(-v0));
                            float s1 = 1.0f / (1.0f + __expf(-v1));
                            ((uint32_t*)g_gate16)[(size_t)i * 128 + (cy - 2) * 64 +
                                                  wn * 16 + nt * 4 + tig] = packh(s0, s1);
                        }
                    }
                }
            }
            #pragma unroll
            for (int a = 0; a < 4; a++)
                #pragma unroll
                for (int bb = 0; bb < 4; bb++)
                    #pragma unroll
                    for (int qq = 0; qq < 4; qq++) acc[a][bb][qq] = 0.0f;
        }
    }
}

// ---------------- K2: warp-per-8-rows LN(z) + @W2t -> b[h][j][i] ----------------
#define LNZ_ROWS 8
__global__ __launch_bounds__(256) void ln_z_warp(const float* __restrict__ z,
                                                 const float* __restrict__ gz,
                                                 const float* __restrict__ bz) {
    int wg = (blockIdx.x * blockDim.x + threadIdx.x) >> 5;
    int lane = threadIdx.x & 31;
    int row0 = wg * LNZ_ROWS;
    if (row0 >= N_DIM * N_DIM) return;

    float4 gm = __ldg((const float4*)(gz + lane * 4));
    float4 bt = __ldg((const float4*)(bz + lane * 4));
    float4 w2[H_DIM];
    #pragma unroll
    for (int h = 0; h < H_DIM; h++)
        w2[h] = __ldg((const float4*)(g_w2t + h * CZ + lane * 4));

    #pragma unroll 1
    for (int r = 0; r < LNZ_ROWS; r++) {
        int row = row0 + r;
        int i = row / N_DIM, j = row % N_DIM;

        float4 x = *(const float4*)(z + (size_t)row * CZ + lane * 4);
        float s  = x.x + x.y + x.z + x.w;
        float ss = x.x * x.x + x.y * x.y + x.z * x.z + x.w * x.w;
        #pragma unroll
        for (int o = 16; o > 0; o >>= 1) {
            s  += __shfl_xor_sync(0xffffffffu, s,  o);
            ss += __shfl_xor_sync(0xffffffffu, ss, o);
        }
        float mu  = s * (1.0f / 128.0f);
        float var = ss * (1.0f / 128.0f) - mu * mu;
        float inv = rsqrtf(var + 1e-5f);

        float zn0 = (x.x - mu) * inv * gm.x + bt.x;
        float zn1 = (x.y - mu) * inv * gm.y + bt.y;
        float zn2 = (x.z - mu) * inv * gm.z + bt.z;
        float zn3 = (x.w - mu) * inv * gm.w + bt.w;

        float acc[H_DIM];
        #pragma unroll
        for (int h = 0; h < H_DIM; h++)
            acc[h] = zn0 * w2[h].x + zn1 * w2[h].y + zn2 * w2[h].z + zn3 * w2[h].w;

        #pragma unroll
        for (int h = 0; h < 4; h++) {
            float v = (lane & 16) ? acc[h] : acc[h + 4];
            float o = __shfl_xor_sync(0xffffffffu, v, 16);
            acc[h] = ((lane & 16) ? acc[h + 4] : acc[h]) + o;
        }
        #pragma unroll
        for (int h = 0; h < 2; h++) {
            float v = (lane & 8) ? acc[h] : acc[h + 2];
            float o = __shfl_xor_sync(0xffffffffu, v, 8);
            acc[h] = ((lane & 8) ? acc[h + 2] : acc[h]) + o;
        }
        {
            float v = (lane & 4) ? acc[0] : acc[1];
            float o = __shfl_xor_sync(0xffffffffu, v, 4);
            acc[0] = ((lane & 4) ? acc[1] : acc[0]) + o;
        }
        acc[0] += __shfl_xor_sync(0xffffffffu, acc[0], 2);
        acc[0] += __shfl_xor_sync(0xffffffffu, acc[0], 1);

        if ((lane & 3) == 0) {
            int h = lane >> 2;
            g_b[((size_t)h * N_DIM + j) * N_DIM + i] = acc[0];
        }
    }
}

// ---------------- K3: softmax over i, write w[h][i][j] fp16 -----------------------
__global__ void softmax_kernel() {
    __shared__ float redm[4];
    __shared__ float reds[4];
    int j = blockIdx.x;
    int h = blockIdx.y;
    int t = threadIdx.x;
    const float* col = g_b + ((size_t)h * N_DIM + j) * N_DIM;
    float v0 = col[t], v1 = col[t + 128], v2 = col[t + 256];
    float mx = fmaxf(v0, fmaxf(v1, v2));
    #pragma unroll
    for (int o = 16; o > 0; o >>= 1) mx = fmaxf(mx, __shfl_xor_sync(0xffffffffu, mx, o));
    int warp = t >> 5, lane = t & 31;
    if (lane == 0) redm[warp] = mx;
    __syncthreads();
    mx = fmaxf(fmaxf(redm[0], redm[1]), fmaxf(redm[2], redm[3]));
    float e0 = __expf(v0 - mx), e1 = __expf(v1 - mx), e2 = __expf(v2 - mx);
    float sm = e0 + e1 + e2;
    #pragma unroll
    for (int o = 16; o > 0; o >>= 1) sm += __shfl_xor_sync(0xffffffffu, sm, o);
    if (lane == 0) reds[warp] = sm;
    __syncthreads();
    float inv = 1.0f / (reds[0] + reds[1] + reds[2] + reds[3]);
    __half* wbase = g_w16 + (size_t)h * N_DIM * N_DIM + j;
    wbase[(size_t)(t)       * N_DIM] = __float2half(e0 * inv);
    wbase[(size_t)(t + 128) * N_DIM] = __float2half(e1 * inv);
    wbase[(size_t)(t + 256) * N_DIM] = __float2half(e2 * inv);
}

// ---------------- K4: fp16-MMA per-head GEMM  wv_h[i,m] = w_h[i,j] @ v_h[j,m] ------
__global__ __launch_bounds__(256, 2) void gemm_wv_mma() {
    __shared__ TS sm[2];
    int t = threadIdx.x;
    int lane = t & 31, w = t >> 5;
    int wm = w & 1, wn = w >> 1;
    int g = lane >> 2, tig = lane & 3;
    int i0 = blockIdx.x * 128;           // 3 i-tiles (fastest -> v-tile L2 reuse)
    int m0 = blockIdx.y * 128;           // 128 m-tiles
    int h  = blockIdx.z;
    const __half* A = g_w16 + (size_t)h * N_DIM * N_DIM;              // [i][j] fp16
    const uint32_t* Bv = g_v32 + (size_t)h * (VROWS * M_DIM);         // [j2][m] pairs

    uint32_t sA[2] = {smem_u32(sm[0].As), smem_u32(sm[1].As)};
    uint32_t sB[2] = {smem_u32(sm[0].Bs), smem_u32(sm[1].Bs)};

    float acc[4][4][4];
    #pragma unroll
    for (int a = 0; a < 4; a++)
        #pragma unroll
        for (int b = 0; b < 4; b++)
            #pragma unroll
            for (int q = 0; q < 4; q++) acc[a][b][q] = 0.0f;

    const __half* Abase = A + (size_t)i0 * N_DIM;
    const uint32_t* Bbase = Bv + m0;

    stage_f16(sA[0], sB[0], t, Abase, N_DIM, Bbase, M_DIM);
    CP_COMMIT();

    #pragma unroll 1
    for (int c = 0; c < 12; c++) {
        int b = c & 1;
        if (c + 1 < 12)
            stage_f16(sA[1 - b], sB[1 - b], t,
                      Abase + (c + 1) * 32, N_DIM,
                      Bbase + (size_t)(c + 1) * 16 * M_DIM, M_DIM);
        CP_COMMIT();
        if (c + 1 < 12) { CP_WAIT1(); } else { CP_WAIT0(); }
        __syncthreads();
        mma_tile32h(acc, &sm[b], wm, wn, g, tig);
        __syncthreads();
    }

    uint32_t* dsth = (uint32_t*)g_wv16 + (size_t)h * N_DIM * (M_DIM / 2);
    #pragma unroll
    for (int mt = 0; mt < 4; mt++) {
        int r = i0 + wm * 64 + mt * 16 + g;
        #pragma unroll
        for (int nt = 0; nt < 4; nt++) {
            int colw = (m0 + wn * 32 + nt * 8 + 2 * tig) >> 1;
            dsth[(size_t)r * (M_DIM / 2) + colw] =
                packh(acc[mt][nt][0], acc[mt][nt][1]);
            dsth[(size_t)(r + 8) * (M_DIM / 2) + colw] =
                packh(acc[mt][nt][2], acc[mt][nt][3]);
        }
    }
}

// ---------------- K5: fp16-MMA  out[r,64] = (gate*wv_gather) @ W4 (R15 version) -----
__global__ __launch_bounds__(256) void final_mma(float* __restrict__ out) {
    __shared__ uint32_t Os[128][20];
    __shared__ uint32_t Ws[16][72];
    int t = threadIdx.x;
    int lane = t & 31, w = t >> 5;
    int wm = w >> 1, wn = w & 1;
    int g = lane >> 2, tig = lane & 3;
    int r0 = blockIdx.x * 128;

    float acc[2][4][4];
    #pragma unroll
    for (int a = 0; a < 2; a++)
        #pragma unroll
        for (int b = 0; b < 4; b++)
            #pragma unroll
            for (int q = 0; q < 4; q++) acc[a][b][q] = 0.0f;

    for (int k0 = 0; k0 < HC; k0 += 32) {
        int h = k0 >> 5;
        {
            int row = t >> 1, kh = (t & 1) * 16;
            int r = r0 + row;
            int s = r / N_DIM, n = r % N_DIM;
            const uint32_t* wvp = (const uint32_t*)g_wv16 +
                ((size_t)(h * N_DIM + n) * M_DIM + s * C_DIM + kh) / 2;
            const uint32_t* gtp = (const uint32_t*)g_gate16 +
                ((size_t)r * HC + k0 + kh) / 2;
            uint4 wv0 = *(const uint4*)wvp;
            uint4 wv1 = *(const uint4*)(wvp + 4);
            uint4 gt0 = *(const uint4*)gtp;
            uint4 gt1 = *(const uint4*)(gtp + 4);
            uint32_t* d = &Os[row][(t & 1) * 8];
            const uint32_t* wvw = (const uint32_t*)&wv0;
            const uint32_t* gtw = (const uint32_t*)&gt0;
            #pragma unroll
            for (int u = 0; u < 4; u++) {
                __half2 p = __hmul2(*(const __half2*)&wvw[u], *(const __half2*)&gtw[u]);
                d[u] = *(uint32_t*)&p;
            }
            const uint32_t* wvw1 = (const uint32_t*)&wv1;
            const uint32_t* gtw1 = (const uint32_t*)&gt1;
            #pragma unroll
            for (int u = 0; u < 4; u++) {
                __half2 p = __hmul2(*(const __half2*)&wvw1[u], *(const __half2*)&gtw1[u]);
                d[4 + u] = *(uint32_t*)&p;
            }
        }
        {
            int kr = t >> 4, cw = (t & 15) * 4;
            *(uint4*)&Ws[kr][cw] = *(const uint4*)(g_w4h + (size_t)(16 * h + kr) * CM + cw);
        }
        __syncthreads();
        #pragma unroll
        for (int kc = 0; kc < 2; kc++) {
            uint32_t af[2][4], bf[4][2];
            #pragma unroll
            for (int mt = 0; mt < 2; mt++) {
                int r = wm * 32 + mt * 16;
                af[mt][0] = Os[r + g][kc * 8 + tig];
                af[mt][1] = Os[r + g + 8][kc * 8 + tig];
                af[mt][2] = Os[r + g][kc * 8 + tig + 4];
                af[mt][3] = Os[r + g + 8][kc * 8 + tig + 4];
            }
            #pragma unroll
            for (int nt = 0; nt < 4; nt++) {
                int cc = wn * 32 + nt * 8 + g;
                bf[nt][0] = Ws[kc * 8 + tig][cc];
                bf[nt][1] = Ws[kc * 8 + tig + 4][cc];
            }
            #pragma unroll
            for (int mt = 0; mt < 2; mt++)
                #pragma unroll
                for (int nt = 0; nt < 4; nt++)
                    mma16(acc[mt][nt], af[mt], bf[nt]);
        }
        __syncthreads();
    }

    #pragma unroll
    for (int mt = 0; mt < 2; mt++) {
        int r = r0 + wm * 32 + mt * 16 + g;
        #pragma unroll
        for (int nt = 0; nt < 4; nt++) {
            int col = wn * 32 + nt * 8 + 2 * tig;
            float2 v0 = {acc[mt][nt][0], acc[mt][nt][1]};
            float2 v1 = {acc[mt][nt][2], acc[mt][nt][3]};
            *(float2*)(out + (size_t)r * CM + col) = v0;
            *(float2*)(out + (size_t)(r + 8) * CM + col) = v1;
        }
    }
}

// ---------------- launch ----------------
extern "C" void kernel_launch(void* const* d_in, const int* in_sizes, int n_in,
                              void* d_out, int out_size) {
    const float* m_si    = (const float*)d_in[0];
    const float* z_ij    = (const float*)d_in[1];
    const float* gamma_m = (const float*)d_in[2];
    const float* beta_m  = (const float*)d_in[3];
    const float* W1      = (const float*)d_in[4];
    const float* gamma_z = (const float*)d_in[5];
    const float* beta_z  = (const float*)d_in[6];
    const float* W2      = (const float*)d_in[7];
    const float* W3      = (const float*)d_in[8];
    const float* W4      = (const float*)d_in[9];
    float* out = (float*)d_out;

    round_weights<<<32, 256>>>(W1, W3, W4, W2);
    ln_m_kernel<<<SN / 8, 256>>>(m_si, gamma_m, beta_m);
    ln_z_warp<<<(N_DIM * N_DIM) / (8 * LNZ_ROWS), 256>>>(z_ij, gamma_z, beta_z);
    gemm_mw_mma<<<SN / 128, 256>>>();
    softmax_kernel<<<dim3(N_DIM, H_DIM), 128>>>();
    gemm_wv_mma<<<dim3(N_DIM / 128, M_DIM / 128, H_DIM), 256>>>();
    final_mma<<<SN / 128, 256>>>(out);
}